// round 13
// baseline (speedup 1.0000x reference)
#include <cuda_runtime.h>
#include <math.h>

#define D 64
#define S 8
#define EPB 32        // elems per tile (both gather and transform)
#define NT 256
#define XP 68         // x row pitch in transform shared
#define HP 33         // h col-major pitch
#define MAXB 65536
#define MAXTILES (MAXB / EPB)

typedef unsigned long long ull;

// scratch for aggregated pre-transform vectors + tile-ready flags
__device__ float g_xu[MAXB * D];
__device__ float g_xv[MAXB * D];
__device__ int   g_flag[MAXTILES];

__device__ __forceinline__ float hsum8(float p) {
    p += __shfl_xor_sync(0xffffffffu, p, 4, 8);
    p += __shfl_xor_sync(0xffffffffu, p, 2, 8);
    p += __shfl_xor_sync(0xffffffffu, p, 1, 8);
    return p;
}
__device__ __forceinline__ ull pk2(float lo, float hi) {
    ull r; asm("mov.b64 %0, {%1, %2};" : "=l"(r) : "f"(lo), "f"(hi)); return r;
}
__device__ __forceinline__ void upk2(float& lo, float& hi, ull v) {
    asm("mov.b64 {%0, %1}, %2;" : "=f"(lo), "=f"(hi) : "l"(v));
}
__device__ __forceinline__ void fma2(ull& a, ull x, ull w) {
    asm("fma.rn.f32x2 %0, %1, %2, %0;" : "+l"(a) : "l"(x), "l"(w));
}

__global__ void reset_flags(int ntiles) {
    const int i = blockIdx.x * blockDim.x + threadIdx.x;
    if (i < ntiles) g_flag[i] = 0;
}

// dynamic shared: gather path uses first 2048 floats; transform uses 12544 floats
#define SMEM_FLOATS 12544

__global__ __launch_bounds__(NT)
void sestkgcn_fused(
    const int* __restrict__ U, const int* __restrict__ V,
    const float* __restrict__ usr_feat, const float* __restrict__ item_feat,
    const float* __restrict__ rel_feat,
    const int* __restrict__ n_uu, const float* __restrict__ uu_st,
    const int* __restrict__ n_ui, const float* __restrict__ ui_rat,
    const float* __restrict__ ui_vot, const float* __restrict__ ui_tim,
    const int* __restrict__ n_iu, const float* __restrict__ iu_rat,
    const float* __restrict__ iu_vot, const float* __restrict__ iu_tim,
    const int* __restrict__ n_ii, const int* __restrict__ n_ir,
    const float* __restrict__ Wu, const float* __restrict__ bu,
    const float* __restrict__ Wv, const float* __restrict__ bv,
    float* __restrict__ out, int batch, int ntiles)
{
    extern __shared__ __align__(16) float smem[];
    const int tid = threadIdx.x;

    if ((int)blockIdx.x < ntiles) {
        // ======================= GATHER PATH =======================
        int*   ovl  = (int*)smem;
        float* swtp = smem;
        const int ebase = blockIdx.x * EPB;
        const float4* __restrict__ uf4 = (const float4*)usr_feat;
        const float4* __restrict__ if4 = (const float4*)item_feat;
        const float4* __restrict__ rf4 = (const float4*)rel_feat;

        // phase 1: softmax weights + neighbor indices
        if (tid < 96) {
            const int pe = tid / 3, side = tid - 3 * pe;
            int Ep = ebase + pe; if (Ep > batch - 1) Ep = batch - 1;
            float raw[S];
            if (side == 0) {
                const int u = U[Ep];
#pragma unroll
                for (int s = 0; s < S; s++) raw[s] = uu_st[u * S + s];
            } else if (side == 1) {
                const int u = U[Ep];
#pragma unroll
                for (int s = 0; s < S; s++)
                    raw[s] = ui_rat[u * S + s] * ui_vot[u * S + s] * ui_tim[u * S + s];
            } else {
                const int v = V[Ep];
#pragma unroll
                for (int s = 0; s < S; s++)
                    raw[s] = iu_rat[v * S + s] * iu_vot[v * S + s] * iu_tim[v * S + s];
            }
            float m = raw[0];
#pragma unroll
            for (int s = 1; s < S; s++) m = fmaxf(m, raw[s]);
            float wv[S], sum = 0.f;
#pragma unroll
            for (int s = 0; s < S; s++) { wv[s] = __expf(raw[s] - m); sum += wv[s]; }
            const float inv = __fdividef(1.0f, sum);
#pragma unroll
            for (int s = 0; s < S; s++) swtp[1280 + pe * 24 + side * 8 + s] = wv[s] * inv;
        } else {
            const int base = (tid - 96) * 8;
#pragma unroll
            for (int j = 0; j < 8; j++) {
                const int i = base + j;
                const int pe = i / 40, slot = i - 40 * pe;
                int Ep = ebase + pe; if (Ep > batch - 1) Ep = batch - 1;
                if (slot < 32) {
                    const int set = slot >> 3, s = slot & 7;
                    int idx;
                    if (set == 0)      idx = n_uu[U[Ep] * S + s];
                    else if (set == 1) idx = n_ui[U[Ep] * S + s];
                    else if (set == 2) idx = n_iu[V[Ep] * S + s];
                    else               idx = n_ii[V[Ep] * S + s];
                    ovl[pe * 32 + set * 8 + s] = idx;
                } else {
                    ovl[1024 + pe * 8 + (slot - 32)] = n_ir[V[Ep] * S + (slot - 32)];
                }
            }
        }
        __syncthreads();

        // phase 2: gathers + aggregation (8 threads/elem)
        const int e = tid >> 3, h = tid & 7;
        const int E = ebase + e;
        const int Ec = (E < batch) ? E : (batch - 1);
        const int u = U[Ec], v = V[Ec];

        const float4 ueA = uf4[u * 16 + 2 * h];
        const float4 ueB = uf4[u * 16 + 2 * h + 1];
        float4 xuA = ueA, xuB = ueB;
#pragma unroll
        for (int s = 0; s < S; s++) {
            const float w = swtp[1280 + e * 24 + s];
            const int id = ovl[e * 32 + s];
            const float4 nA = uf4[id * 16 + 2 * h], nB = uf4[id * 16 + 2 * h + 1];
            xuA.x = fmaf(w, nA.x, xuA.x); xuA.y = fmaf(w, nA.y, xuA.y);
            xuA.z = fmaf(w, nA.z, xuA.z); xuA.w = fmaf(w, nA.w, xuA.w);
            xuB.x = fmaf(w, nB.x, xuB.x); xuB.y = fmaf(w, nB.y, xuB.y);
            xuB.z = fmaf(w, nB.z, xuB.z); xuB.w = fmaf(w, nB.w, xuB.w);
        }
#pragma unroll
        for (int s = 0; s < S; s++) {
            const float w = swtp[1280 + e * 24 + 8 + s];
            const int id = ovl[e * 32 + 8 + s];
            const float4 nA = if4[id * 16 + 2 * h], nB = if4[id * 16 + 2 * h + 1];
            xuA.x = fmaf(w, nA.x, xuA.x); xuA.y = fmaf(w, nA.y, xuA.y);
            xuA.z = fmaf(w, nA.z, xuA.z); xuA.w = fmaf(w, nA.w, xuA.w);
            xuB.x = fmaf(w, nB.x, xuB.x); xuB.y = fmaf(w, nB.y, xuB.y);
            xuB.z = fmaf(w, nB.z, xuB.z); xuB.w = fmaf(w, nB.w, xuB.w);
        }
        float4 xvA = if4[v * 16 + 2 * h], xvB = if4[v * 16 + 2 * h + 1];
#pragma unroll
        for (int s = 0; s < S; s++) {
            const float w = swtp[1280 + e * 24 + 16 + s];
            const int id = ovl[e * 32 + 16 + s];
            const float4 nA = uf4[id * 16 + 2 * h], nB = uf4[id * 16 + 2 * h + 1];
            xvA.x = fmaf(w, nA.x, xvA.x); xvA.y = fmaf(w, nA.y, xvA.y);
            xvA.z = fmaf(w, nA.z, xvA.z); xvA.w = fmaf(w, nA.w, xvA.w);
            xvB.x = fmaf(w, nB.x, xvB.x); xvB.y = fmaf(w, nB.y, xvB.y);
            xvB.z = fmaf(w, nB.z, xvB.z); xvB.w = fmaf(w, nB.w, xvB.w);
        }

        // KG attention
        float att[S];
#pragma unroll
        for (int s = 0; s < S; s++) {
            const int id = ovl[1024 + e * 8 + s];
            const float4 rA = rf4[id * 16 + 2 * h], rB = rf4[id * 16 + 2 * h + 1];
            float p = ueA.x * rA.x;
            p = fmaf(ueA.y, rA.y, p); p = fmaf(ueA.z, rA.z, p); p = fmaf(ueA.w, rA.w, p);
            p = fmaf(ueB.x, rB.x, p); p = fmaf(ueB.y, rB.y, p);
            p = fmaf(ueB.z, rB.z, p); p = fmaf(ueB.w, rB.w, p);
            att[s] = p;
        }
#pragma unroll
        for (int s = 0; s < S; s++) att[s] = hsum8(att[s]);
        {
            float m = att[0];
#pragma unroll
            for (int s = 1; s < S; s++) m = fmaxf(m, att[s]);
            float wv[S], sum = 0.f;
#pragma unroll
            for (int s = 0; s < S; s++) { wv[s] = __expf(att[s] - m); sum += wv[s]; }
            const float inv = __fdividef(1.0f, sum);
            int ids[S];
#pragma unroll
            for (int s = 0; s < S; s++) ids[s] = ovl[e * 32 + 24 + s];
#pragma unroll
            for (int s = 0; s < S; s++) {
                const float w = wv[s] * inv;
                const float4 nA = if4[ids[s] * 16 + 2 * h], nB = if4[ids[s] * 16 + 2 * h + 1];
                xvA.x = fmaf(w, nA.x, xvA.x); xvA.y = fmaf(w, nA.y, xvA.y);
                xvA.z = fmaf(w, nA.z, xvA.z); xvA.w = fmaf(w, nA.w, xvA.w);
                xvB.x = fmaf(w, nB.x, xvB.x); xvB.y = fmaf(w, nB.y, xvB.y);
                xvB.z = fmaf(w, nB.z, xvB.z); xvB.w = fmaf(w, nB.w, xvB.w);
            }
        }

        if (E < batch) {
            *(float4*)&g_xu[E * D + 8 * h]     = xuA;
            *(float4*)&g_xu[E * D + 8 * h + 4] = xuB;
            *(float4*)&g_xv[E * D + 8 * h]     = xvA;
            *(float4*)&g_xv[E * D + 8 * h + 4] = xvB;
        }
        __threadfence();
        __syncthreads();
        if (tid == 0) {
            asm volatile("st.global.release.gpu.b32 [%0], %1;"
                         :: "l"(&g_flag[blockIdx.x]), "r"(1) : "memory");
        }
    } else {
        // ======================= TRANSFORM PATH =======================
        float* sW = smem;          // 8192 floats
        float* sx = smem + 8192;   // 4352 floats
        const int t = (int)blockIdx.x - ntiles;
        const int eb2 = t * EPB;

        // W copy first (independent of flag)
#pragma unroll
        for (int i = tid; i < 1024; i += NT) {
            ((float4*)sW)[i]        = ((const float4*)Wu)[i];
            ((float4*)sW)[1024 + i] = ((const float4*)Wv)[i];
        }

        // wait for this tile's gather
        if (tid == 0) {
            int v;
            do {
                asm volatile("ld.global.acquire.gpu.b32 %0, [%1];"
                             : "=r"(v) : "l"(&g_flag[t]) : "memory");
            } while (v == 0);
        }
        __syncthreads();   // W ready + flag observed

        // stage x from scratch into pitched shared (coalesced)
#pragma unroll
        for (int idx = tid; idx < 512; idx += NT) {   // 32 elems x 16 quads
            const int e2 = idx >> 4, kq = idx & 15;
            int E = eb2 + e2; if (E > batch - 1) E = batch - 1;
            *(float4*)&sx[XP * e2 + 4 * kq]        = *(const float4*)&g_xu[E * D + 4 * kq];
            *(float4*)&sx[2176 + XP * e2 + 4 * kq] = *(const float4*)&g_xv[E * D + 4 * kq];
        }
        __syncthreads();   // x ready

        const int side = tid >> 7;
        const int sid  = tid & 127;
        const int wI   = sid >> 5, l = sid & 31;
        const int tq   = l >> 3, eq = l & 7;
        const int cg   = 4 * wI + tq;
        const float* __restrict__ Ws = sW + side * 4096;
        const float* __restrict__ xs = sx + side * 2176;
        const float4 b4 = ((const float4*)(side ? bv : bu))[cg];

        ull a01_0 = pk2(b4.x, b4.y), a23_0 = pk2(b4.z, b4.w);
        ull a01_1 = a01_0, a23_1 = a23_0;
        ull a01_2 = a01_0, a23_2 = a23_0;
        ull a01_3 = a01_0, a23_3 = a23_0;

#pragma unroll 4
        for (int a = 0; a < 16; a++) {
            const float4 x0 = *(const float4*)&xs[XP * eq        + 4 * a];
            const float4 x1 = *(const float4*)&xs[XP * (eq + 8)  + 4 * a];
            const float4 x2 = *(const float4*)&xs[XP * (eq + 16) + 4 * a];
            const float4 x3 = *(const float4*)&xs[XP * (eq + 24) + 4 * a];
            const float xa0[4] = {x0.x, x0.y, x0.z, x0.w};
            const float xa1[4] = {x1.x, x1.y, x1.z, x1.w};
            const float xa2[4] = {x2.x, x2.y, x2.z, x2.w};
            const float xa3[4] = {x3.x, x3.y, x3.z, x3.w};
#pragma unroll
            for (int j = 0; j < 4; j++) {
                const float4 w4 = *(const float4*)&Ws[(4 * a + j) * 64 + 4 * cg];
                const ull wp0 = pk2(w4.x, w4.y), wp1 = pk2(w4.z, w4.w);
                ull xb;
                xb = pk2(xa0[j], xa0[j]); fma2(a01_0, xb, wp0); fma2(a23_0, xb, wp1);
                xb = pk2(xa1[j], xa1[j]); fma2(a01_1, xb, wp0); fma2(a23_1, xb, wp1);
                xb = pk2(xa2[j], xa2[j]); fma2(a01_2, xb, wp0); fma2(a23_2, xb, wp1);
                xb = pk2(xa3[j], xa3[j]); fma2(a01_3, xb, wp0); fma2(a23_3, xb, wp1);
            }
        }
        __syncthreads();   // x reads done -> overwrite with h (col-major)
        {
            float* __restrict__ hs = sx + side * 2176;
            float h0, h1, h2, h3;
#define HSTORE(A01, A23, EE) \
            upk2(h0, h1, A01); upk2(h2, h3, A23); \
            hs[HP * (4 * cg + 0) + (EE)] = fmaxf(h0, 0.f); \
            hs[HP * (4 * cg + 1) + (EE)] = fmaxf(h1, 0.f); \
            hs[HP * (4 * cg + 2) + (EE)] = fmaxf(h2, 0.f); \
            hs[HP * (4 * cg + 3) + (EE)] = fmaxf(h3, 0.f);
            HSTORE(a01_0, a23_0, eq)
            HSTORE(a01_1, a23_1, eq + 8)
            HSTORE(a01_2, a23_2, eq + 16)
            HSTORE(a01_3, a23_3, eq + 24)
#undef HSTORE
        }
        __syncthreads();   // h ready

        {
            const int e = tid >> 3, oct = tid & 7;
            float p = 0.f;
#pragma unroll
            for (int j = 0; j < 8; j++) {
                const int c = 8 * oct + j;
                p = fmaf(sx[HP * c + e], sx[2176 + HP * c + e], p);
            }
            p = hsum8(p);
            const int E = eb2 + e;
            if (oct == 0 && E < batch)
                out[E] = __fdividef(5.0f, 1.0f + __expf(-p));
        }
    }
}

extern "C" void kernel_launch(void* const* d_in, const int* in_sizes, int n_in,
                              void* d_out, int out_size) {
    const int*   U        = (const int*)  d_in[0];
    const int*   V        = (const int*)  d_in[1];
    const float* usr_feat = (const float*)d_in[2];
    const float* item_feat= (const float*)d_in[3];
    const float* rel_feat = (const float*)d_in[4];
    const int*   n_uu     = (const int*)  d_in[5];
    const float* uu_st    = (const float*)d_in[6];
    const int*   n_ui     = (const int*)  d_in[7];
    const float* ui_rat   = (const float*)d_in[8];
    const float* ui_vot   = (const float*)d_in[9];
    const float* ui_tim   = (const float*)d_in[10];
    const int*   n_iu     = (const int*)  d_in[11];
    const float* iu_rat   = (const float*)d_in[12];
    const float* iu_vot   = (const float*)d_in[13];
    const float* iu_tim   = (const float*)d_in[14];
    const int*   n_ii     = (const int*)  d_in[15];
    const int*   n_ir     = (const int*)  d_in[16];
    const float* Wu       = (const float*)d_in[17];
    const float* bu       = (const float*)d_in[18];
    const float* Wv       = (const float*)d_in[19];
    const float* bv       = (const float*)d_in[20];
    float* out = (float*)d_out;

    int batch = in_sizes[0];
    if (batch > MAXB) batch = MAXB;
    const int ntiles = (batch + EPB - 1) / EPB;

    reset_flags<<<(ntiles + 255) / 256, 256>>>(ntiles);

    const int smem_bytes = SMEM_FLOATS * (int)sizeof(float);
    cudaFuncSetAttribute(sestkgcn_fused,
                         cudaFuncAttributeMaxDynamicSharedMemorySize, smem_bytes);
    sestkgcn_fused<<<2 * ntiles, NT, smem_bytes>>>(
        U, V, usr_feat, item_feat, rel_feat,
        n_uu, uu_st, n_ui, ui_rat, ui_vot, ui_tim,
        n_iu, iu_rat, iu_vot, iu_tim, n_ii, n_ir,
        Wu, bu, Wv, bv, out, batch, ntiles);
}

// round 15
// speedup vs baseline: 1.6296x; 1.6296x over previous
#include <cuda_runtime.h>
#include <math.h>

#define D 64
#define S 8
#define NT 256
#define EPB 16        // elems per gather block (16 threads/elem)
#define EP2 64        // elems per transform block
#define SUBT 32       // transform subtile
#define XP 68         // x row pitch in transform shared
#define HP 33         // h col-major pitch
#define MAXB 65536

typedef unsigned long long ull;

// 32 MB scratch for aggregated pre-transform vectors
__device__ float g_xu[MAXB * D];
__device__ float g_xv[MAXB * D];

__device__ __forceinline__ float hsum8(float p) {
    p += __shfl_xor_sync(0xffffffffu, p, 4, 8);
    p += __shfl_xor_sync(0xffffffffu, p, 2, 8);
    p += __shfl_xor_sync(0xffffffffu, p, 1, 8);
    return p;
}
__device__ __forceinline__ float hsum16(float p) {
    p += __shfl_xor_sync(0xffffffffu, p, 8, 16);
    p += __shfl_xor_sync(0xffffffffu, p, 4, 16);
    p += __shfl_xor_sync(0xffffffffu, p, 2, 16);
    p += __shfl_xor_sync(0xffffffffu, p, 1, 16);
    return p;
}
__device__ __forceinline__ ull pk2(float lo, float hi) {
    ull r; asm("mov.b64 %0, {%1, %2};" : "=l"(r) : "f"(lo), "f"(hi)); return r;
}
__device__ __forceinline__ void upk2(float& lo, float& hi, ull v) {
    asm("mov.b64 {%0, %1}, %2;" : "=f"(lo), "=f"(hi) : "l"(v));
}
__device__ __forceinline__ void fma2(ull& a, ull x, ull w) {
    asm("fma.rn.f32x2 %0, %1, %2, %0;" : "+l"(a) : "l"(x), "l"(w));
}

// ======================= kernel 1: gather + aggregate (16 thr/elem) ===========
__global__ __launch_bounds__(NT, 5)
void gather_kernel(
    const int* __restrict__ U, const int* __restrict__ V,
    const float* __restrict__ usr_feat, const float* __restrict__ item_feat,
    const float* __restrict__ rel_feat,
    const int* __restrict__ n_uu, const float* __restrict__ uu_st,
    const int* __restrict__ n_ui, const float* __restrict__ ui_rat,
    const float* __restrict__ ui_vot, const float* __restrict__ ui_tim,
    const int* __restrict__ n_iu, const float* __restrict__ iu_rat,
    const float* __restrict__ iu_vot, const float* __restrict__ iu_tim,
    const int* __restrict__ n_ii, const int* __restrict__ n_ir,
    int batch)
{
    // overlay: snid ints [0..511] (pe*32+set*8+s), srid ints [512..639] (pe*8+s),
    //          swt floats [640..1023] (pe*24+side*8+s)
    __shared__ float sovl[1024];
    int*   ovl  = (int*)sovl;
    float* swtp = sovl;

    const int tid = threadIdx.x;
    const int ebase = blockIdx.x * EPB;
    const float4* __restrict__ uf4 = (const float4*)usr_feat;
    const float4* __restrict__ if4 = (const float4*)item_feat;
    const float4* __restrict__ rf4 = (const float4*)rel_feat;

    // ---- phase 1: softmax weights + neighbor indices ----
    if (tid < 48) {
        const int pe = tid / 3, side = tid - 3 * pe;
        int Ep = ebase + pe; if (Ep > batch - 1) Ep = batch - 1;
        float raw[S];
        if (side == 0) {
            const int u = U[Ep];
#pragma unroll
            for (int s = 0; s < S; s++) raw[s] = uu_st[u * S + s];
        } else if (side == 1) {
            const int u = U[Ep];
#pragma unroll
            for (int s = 0; s < S; s++)
                raw[s] = ui_rat[u * S + s] * ui_vot[u * S + s] * ui_tim[u * S + s];
        } else {
            const int v = V[Ep];
#pragma unroll
            for (int s = 0; s < S; s++)
                raw[s] = iu_rat[v * S + s] * iu_vot[v * S + s] * iu_tim[v * S + s];
        }
        float m = raw[0];
#pragma unroll
        for (int s = 1; s < S; s++) m = fmaxf(m, raw[s]);
        float wv[S], sum = 0.f;
#pragma unroll
        for (int s = 0; s < S; s++) { wv[s] = __expf(raw[s] - m); sum += wv[s]; }
        const float inv = __fdividef(1.0f, sum);
#pragma unroll
        for (int s = 0; s < S; s++) swtp[640 + pe * 24 + side * 8 + s] = wv[s] * inv;
    } else if (tid >= 96) {
        const int base = (tid - 96) * 4;   // 160 threads x 4 = 640 = 16 elems x 40 slots
#pragma unroll
        for (int j = 0; j < 4; j++) {
            const int i = base + j;
            const int pe = i / 40, slot = i - 40 * pe;
            int Ep = ebase + pe; if (Ep > batch - 1) Ep = batch - 1;
            if (slot < 32) {
                const int set = slot >> 3, s = slot & 7;
                int idx;
                if (set == 0)      idx = n_uu[U[Ep] * S + s];
                else if (set == 1) idx = n_ui[U[Ep] * S + s];
                else if (set == 2) idx = n_iu[V[Ep] * S + s];
                else               idx = n_ii[V[Ep] * S + s];
                ovl[pe * 32 + set * 8 + s] = idx;
            } else {
                ovl[512 + pe * 8 + (slot - 32)] = n_ir[V[Ep] * S + (slot - 32)];
            }
        }
    }
    __syncthreads();

    // ---- phase 2: gathers + aggregation (16 threads/elem, 1 float4/thread/row) ----
    const int e = tid >> 4, h = tid & 15;
    const int E = ebase + e;
    const int Ec = (E < batch) ? E : (batch - 1);
    const int u = U[Ec], v = V[Ec];

    const float4 ue = uf4[u * 16 + h];
    float4 xu = ue;
#pragma unroll
    for (int s = 0; s < S; s++) {
        const float w = swtp[640 + e * 24 + s];
        const float4 n = uf4[ovl[e * 32 + s] * 16 + h];
        xu.x = fmaf(w, n.x, xu.x); xu.y = fmaf(w, n.y, xu.y);
        xu.z = fmaf(w, n.z, xu.z); xu.w = fmaf(w, n.w, xu.w);
    }
#pragma unroll
    for (int s = 0; s < S; s++) {
        const float w = swtp[640 + e * 24 + 8 + s];
        const float4 n = if4[ovl[e * 32 + 8 + s] * 16 + h];
        xu.x = fmaf(w, n.x, xu.x); xu.y = fmaf(w, n.y, xu.y);
        xu.z = fmaf(w, n.z, xu.z); xu.w = fmaf(w, n.w, xu.w);
    }
    float4 xv = if4[v * 16 + h];
#pragma unroll
    for (int s = 0; s < S; s++) {
        const float w = swtp[640 + e * 24 + 16 + s];
        const float4 n = uf4[ovl[e * 32 + 16 + s] * 16 + h];
        xv.x = fmaf(w, n.x, xv.x); xv.y = fmaf(w, n.y, xv.y);
        xv.z = fmaf(w, n.z, xv.z); xv.w = fmaf(w, n.w, xv.w);
    }

    // KG attention: att[s] = dot(u_emb, rel_s) over 64 dims (16 lanes x 4)
    float att[S];
#pragma unroll
    for (int s = 0; s < S; s++) {
        const float4 r = rf4[ovl[512 + e * 8 + s] * 16 + h];
        float p = ue.x * r.x;
        p = fmaf(ue.y, r.y, p); p = fmaf(ue.z, r.z, p); p = fmaf(ue.w, r.w, p);
        att[s] = p;
    }
#pragma unroll
    for (int s = 0; s < S; s++) att[s] = hsum16(att[s]);
    {
        float m = att[0];
#pragma unroll
        for (int s = 1; s < S; s++) m = fmaxf(m, att[s]);
        float wv[S], sum = 0.f;
#pragma unroll
        for (int s = 0; s < S; s++) { wv[s] = __expf(att[s] - m); sum += wv[s]; }
        const float inv = __fdividef(1.0f, sum);
#pragma unroll
        for (int s = 0; s < S; s++) {
            const float w = wv[s] * inv;
            const float4 n = if4[ovl[e * 32 + 24 + s] * 16 + h];
            xv.x = fmaf(w, n.x, xv.x); xv.y = fmaf(w, n.y, xv.y);
            xv.z = fmaf(w, n.z, xv.z); xv.w = fmaf(w, n.w, xv.w);
        }
    }

    // coalesced store to scratch
    if (E < batch) {
        *(float4*)&g_xu[E * D + 4 * h] = xu;
        *(float4*)&g_xv[E * D + 4 * h] = xv;
    }
}

// ======================= kernel 2: dense transform + score ====================
#define SMEM2_FLOATS 12544

__global__ __launch_bounds__(NT)
void transform_kernel(
    const float* __restrict__ Wu, const float* __restrict__ bu,
    const float* __restrict__ Wv, const float* __restrict__ bv,
    float* __restrict__ out, int batch)
{
    extern __shared__ __align__(16) float smem[];
    float* sW = smem;
    float* sx = smem + 8192;

    const int tid = threadIdx.x;

#pragma unroll
    for (int i = tid; i < 1024; i += NT) {
        ((float4*)sW)[i]        = ((const float4*)Wu)[i];
        ((float4*)sW)[1024 + i] = ((const float4*)Wv)[i];
    }

    const int side = tid >> 7;
    const int sid  = tid & 127;
    const int wI   = sid >> 5, l = sid & 31;
    const int t    = l >> 3, eq = l & 7;
    const int cg   = 4 * wI + t;
    const float* __restrict__ Ws = sW + side * 4096;
    const float* __restrict__ xs = sx + side * 2176;
    const float4 b4 = ((const float4*)(side ? bv : bu))[cg];

#pragma unroll 1
    for (int sub = 0; sub < EP2 / SUBT; sub++) {
        const int eb2 = blockIdx.x * EP2 + sub * SUBT;

        __syncthreads();
#pragma unroll
        for (int idx = tid; idx < 512; idx += NT) {
            const int e2 = idx >> 4, kq = idx & 15;
            int E = eb2 + e2; if (E > batch - 1) E = batch - 1;
            *(float4*)&sx[XP * e2 + 4 * kq]        = *(const float4*)&g_xu[E * D + 4 * kq];
            *(float4*)&sx[2176 + XP * e2 + 4 * kq] = *(const float4*)&g_xv[E * D + 4 * kq];
        }
        __syncthreads();

        ull a01_0 = pk2(b4.x, b4.y), a23_0 = pk2(b4.z, b4.w);
        ull a01_1 = a01_0, a23_1 = a23_0;
        ull a01_2 = a01_0, a23_2 = a23_0;
        ull a01_3 = a01_0, a23_3 = a23_0;

#pragma unroll 4
        for (int a = 0; a < 16; a++) {
            const float4 x0 = *(const float4*)&xs[XP * eq        + 4 * a];
            const float4 x1 = *(const float4*)&xs[XP * (eq + 8)  + 4 * a];
            const float4 x2 = *(const float4*)&xs[XP * (eq + 16) + 4 * a];
            const float4 x3 = *(const float4*)&xs[XP * (eq + 24) + 4 * a];
            const float xa0[4] = {x0.x, x0.y, x0.z, x0.w};
            const float xa1[4] = {x1.x, x1.y, x1.z, x1.w};
            const float xa2[4] = {x2.x, x2.y, x2.z, x2.w};
            const float xa3[4] = {x3.x, x3.y, x3.z, x3.w};
#pragma unroll
            for (int j = 0; j < 4; j++) {
                const float4 w4 = *(const float4*)&Ws[(4 * a + j) * 64 + 4 * cg];
                const ull wp0 = pk2(w4.x, w4.y), wp1 = pk2(w4.z, w4.w);
                ull xb;
                xb = pk2(xa0[j], xa0[j]); fma2(a01_0, xb, wp0); fma2(a23_0, xb, wp1);
                xb = pk2(xa1[j], xa1[j]); fma2(a01_1, xb, wp0); fma2(a23_1, xb, wp1);
                xb = pk2(xa2[j], xa2[j]); fma2(a01_2, xb, wp0); fma2(a23_2, xb, wp1);
                xb = pk2(xa3[j], xa3[j]); fma2(a01_3, xb, wp0); fma2(a23_3, xb, wp1);
            }
        }
        __syncthreads();

        {
            float* __restrict__ hs = sx + side * 2176;
            float h0, h1, h2, h3;
#define HSTORE(A01, A23, EE) \
            upk2(h0, h1, A01); upk2(h2, h3, A23); \
            hs[HP * (4 * cg + 0) + (EE)] = fmaxf(h0, 0.f); \
            hs[HP * (4 * cg + 1) + (EE)] = fmaxf(h1, 0.f); \
            hs[HP * (4 * cg + 2) + (EE)] = fmaxf(h2, 0.f); \
            hs[HP * (4 * cg + 3) + (EE)] = fmaxf(h3, 0.f);
            HSTORE(a01_0, a23_0, eq)
            HSTORE(a01_1, a23_1, eq + 8)
            HSTORE(a01_2, a23_2, eq + 16)
            HSTORE(a01_3, a23_3, eq + 24)
#undef HSTORE
        }
        __syncthreads();

        {
            const int e = tid >> 3, oct = tid & 7;
            float p = 0.f;
#pragma unroll
            for (int j = 0; j < 8; j++) {
                const int c = 8 * oct + j;
                p = fmaf(sx[HP * c + e], sx[2176 + HP * c + e], p);
            }
            p = hsum8(p);
            const int E = eb2 + e;
            if (oct == 0 && E < batch)
                out[E] = __fdividef(5.0f, 1.0f + __expf(-p));
        }
    }
}

extern "C" void kernel_launch(void* const* d_in, const int* in_sizes, int n_in,
                              void* d_out, int out_size) {
    const int*   U        = (const int*)  d_in[0];
    const int*   V        = (const int*)  d_in[1];
    const float* usr_feat = (const float*)d_in[2];
    const float* item_feat= (const float*)d_in[3];
    const float* rel_feat = (const float*)d_in[4];
    const int*   n_uu     = (const int*)  d_in[5];
    const float* uu_st    = (const float*)d_in[6];
    const int*   n_ui     = (const int*)  d_in[7];
    const float* ui_rat   = (const float*)d_in[8];
    const float* ui_vot   = (const float*)d_in[9];
    const float* ui_tim   = (const float*)d_in[10];
    const int*   n_iu     = (const int*)  d_in[11];
    const float* iu_rat   = (const float*)d_in[12];
    const float* iu_vot   = (const float*)d_in[13];
    const float* iu_tim   = (const float*)d_in[14];
    const int*   n_ii     = (const int*)  d_in[15];
    const int*   n_ir     = (const int*)  d_in[16];
    const float* Wu       = (const float*)d_in[17];
    const float* bu       = (const float*)d_in[18];
    const float* Wv       = (const float*)d_in[19];
    const float* bv       = (const float*)d_in[20];
    float* out = (float*)d_out;

    int batch = in_sizes[0];
    if (batch > MAXB) batch = MAXB;

    const int nb1 = (batch + EPB - 1) / EPB;
    gather_kernel<<<nb1, NT>>>(
        U, V, usr_feat, item_feat, rel_feat,
        n_uu, uu_st, n_ui, ui_rat, ui_vot, ui_tim,
        n_iu, iu_rat, iu_vot, iu_tim, n_ii, n_ir, batch);

    const int smem2 = SMEM2_FLOATS * (int)sizeof(float);
    cudaFuncSetAttribute(transform_kernel,
                         cudaFuncAttributeMaxDynamicSharedMemorySize, smem2);
    const int nb2 = (batch + EP2 - 1) / EP2;
    transform_kernel<<<nb2, NT, smem2>>>(Wu, bu, Wv, bv, out, batch);
}